// round 4
// baseline (speedup 1.0000x reference)
#include <cuda_runtime.h>
#include <math.h>

// Scratch SoA (float4-packed) for up to 16384 (view,gaussian) entries.
#define CAP (1 << 14)
__device__ float4 g_cull[CAP];   // (u, v, rad, z)
__device__ float4 g_con[CAP];    // (-0.5*ia, -ib, -0.5*idd, op)
__device__ float4 g_col[CAP];    // (cr, cg, cb, powThresh)

// ---------------------------------------------------------------------------
// Phase 1: per-(view, gaussian) preprocessing
// ---------------------------------------------------------------------------
__global__ void prep_kernel(const float* __restrict__ means,
                            const float* __restrict__ scales,
                            const float* __restrict__ rots,
                            const float* __restrict__ sh,
                            const float* __restrict__ opac,
                            const float* __restrict__ extr,
                            const float* __restrict__ intr,
                            const int* __restrict__ Hp,
                            const int* __restrict__ Wp,
                            int G, int NV)
{
    int i = blockIdx.x * blockDim.x + threadIdx.x;
    if (i >= G * NV) return;
    int vi = i / G;
    int g  = i - vi * G;

    float Wf = (float)(*Wp), Hf = (float)(*Hp);
    const float* E = extr + vi * 16;   // 4x4 row-major
    const float* K = intr + vi * 9;    // 3x3 row-major
    float fx = (K[0] / Wf) * Wf;
    float cx = (K[2] / Wf) * Wf;
    float fy = (K[4] / Hf) * Hf;
    float cy = (K[5] / Hf) * Hf;

    float mx = means[g*3+0], my = means[g*3+1], mz = means[g*3+2];
    float px = E[0]*mx + E[1]*my + E[2]*mz  + E[3];
    float py = E[4]*mx + E[5]*my + E[6]*mz  + E[7];
    float pz = E[8]*mx + E[9]*my + E[10]*mz + E[11];
    float zs = fmaxf(pz, 1e-6f);
    float u = fx * px / zs + cx;
    float v = fy * py / zs + cy;

    float4 q4 = ((const float4*)rots)[g];
    float qw = q4.x, qx = q4.y, qy = q4.z, qz = q4.w;
    float qinv = rsqrtf(qw*qw + qx*qx + qy*qy + qz*qz);
    qw *= qinv; qx *= qinv; qy *= qinv; qz *= qinv;
    float R00 = 1.f - 2.f*(qy*qy + qz*qz), R01 = 2.f*(qx*qy - qw*qz), R02 = 2.f*(qx*qz + qw*qy);
    float R10 = 2.f*(qx*qy + qw*qz), R11 = 1.f - 2.f*(qx*qx + qz*qz), R12 = 2.f*(qy*qz - qw*qx);
    float R20 = 2.f*(qx*qz - qw*qy), R21 = 2.f*(qy*qz + qw*qx), R22 = 1.f - 2.f*(qx*qx + qy*qy);

    float s0 = scales[g*3+0], s1 = scales[g*3+1], s2 = scales[g*3+2];
    float M00=R00*s0, M01=R01*s1, M02=R02*s2;
    float M10=R10*s0, M11=R11*s1, M12=R12*s2;
    float M20=R20*s0, M21=R21*s1, M22=R22*s2;
    float S00 = M00*M00+M01*M01+M02*M02;
    float S01 = M00*M10+M01*M11+M02*M12;
    float S02 = M00*M20+M01*M21+M02*M22;
    float S11 = M10*M10+M11*M11+M12*M12;
    float S12 = M10*M20+M11*M21+M12*M22;
    float S22 = M20*M20+M21*M21+M22*M22;

    float iz  = 1.f / zs;
    float J00 = fx*iz,  J02 = -fx*px*iz*iz;
    float J11 = fy*iz,  J12 = -fy*py*iz*iz;
    float t00 = J00*E[0] + J02*E[8];
    float t01 = J00*E[1] + J02*E[9];
    float t02 = J00*E[2] + J02*E[10];
    float t10 = J11*E[4] + J12*E[8];
    float t11 = J11*E[5] + J12*E[9];
    float t12 = J11*E[6] + J12*E[10];
    float w0 = S00*t00 + S01*t01 + S02*t02;
    float w1 = S01*t00 + S11*t01 + S12*t02;
    float w2 = S02*t00 + S12*t01 + S22*t02;
    float a  = t00*w0 + t01*w1 + t02*w2 + 0.3f;
    float b  = t10*w0 + t11*w1 + t12*w2;
    float x0 = S00*t10 + S01*t11 + S02*t12;
    float x1 = S01*t10 + S11*t11 + S12*t12;
    float x2 = S02*t10 + S12*t11 + S22*t12;
    float d  = t10*x0 + t11*x1 + t12*x2 + 0.3f;

    float det = a*d - b*b;
    float ds  = fmaxf(det, 1e-12f);
    float ia = d/ds, ib = -b/ds, idd = a/ds;
    bool valid = (pz > 0.2f) && (det > 1e-12f);
    float op = valid ? opac[g] : 0.f;

    const float SH_C0 = 0.28209479177387814f;
    float cr = fmaxf(SH_C0 * sh[g*3+0] + 0.5f, 0.f);
    float cg = fmaxf(SH_C0 * sh[g*3+1] + 0.5f, 0.f);
    float cb = fmaxf(SH_C0 * sh[g*3+2] + 0.5f, 0.f);

    // Conservative cull radius: alpha >= 1/255 needs 0.5 d^T C d <= ln(255 op);
    // bound via lmin(C)=1/lmax(cov2D): |d| <= sqrt(2 ln(255 op) lmax(cov2D)).
    float rad = -1.f;
    float thr = 0.f;
    if (op * 255.f > 1.f) {
        float lam = 0.5f*(a+d) + sqrtf(0.25f*(a-d)*(a-d) + b*b);
        float t = logf(255.f * op);
        rad = sqrtf(fmaxf(2.f*t*lam, 0.f)) + 0.05f;
        thr = -t - 1e-4f;   // power < thr  =>  alpha < 1/255 guaranteed
    }

    int o = vi*G + g;
    g_cull[o] = make_float4(u, v, rad, pz);
    g_con[o]  = make_float4(-0.5f*ia, -ib, -0.5f*idd, op);
    g_col[o]  = make_float4(cr, cg, cb, thr);
}

// ---------------------------------------------------------------------------
// Phase 2: per-tile cull + sort + segment-parallel front-to-back compositing.
// 1024 threads = 8 depth segments x 128 pixels (16x8 tile).
// Grid-stride over tiles (tile count known only on device).
// ---------------------------------------------------------------------------
#define NSEG 8
#define NPIX 128
#define NTHR 1024
#define TSX 16
#define TSY 8

__global__ __launch_bounds__(NTHR, 1)
void composite_kernel(float* __restrict__ out,
                      const int* __restrict__ Hp,
                      const int* __restrict__ Wp,
                      int G, int NV)
{
    int W = *Wp, H = *Hp;
    int ntx = (W + TSX - 1) / TSX, nty = (H + TSY - 1) / TSY;
    int totalTiles = ntx * nty * NV;

    extern __shared__ char dsm[];
    unsigned long long* s_key = (unsigned long long*)dsm;       // G * 8
    float4* s_pos = (float4*)(dsm + (size_t)G * 8);             // (u,v,thr,z)
    float4* s_con = s_pos + G;                                  // (-ia/2,-ib,-idd/2,op)
    float4* s_col = s_con + G;                                  // (cr,cg,cb,-)
    __shared__ float4 segC[NSEG][NPIX];
    __shared__ float  segT[NSEG][NPIX];
    __shared__ int s_cnt;

    int tid = threadIdx.x;
    int lane = tid & 31;
    int seg = tid >> 7, pix = tid & (NPIX - 1);
    int lx = pix & (TSX - 1), ly = pix >> 4;

    for (int tile = blockIdx.x; tile < totalTiles; tile += gridDim.x) {
        int vi = tile / (ntx * nty);
        int t2 = tile - vi * ntx * nty;
        int tx = t2 % ntx, ty = t2 / ntx;
        int base = vi * G;

        float tminx = (float)(tx*TSX), tmaxx = (float)(tx*TSX + TSX);
        float tminy = (float)(ty*TSY), tmaxy = (float)(ty*TSY + TSY);

        __syncthreads();
        if (tid == 0) s_cnt = 0;
        __syncthreads();

        // ---- cull: warp-aggregated append of (flipped z bits | index) ----
        for (int gi = tid; gi < G; gi += NTHR) {
            float4 c = g_cull[base + gi];
            bool keep = (c.z > 0.f &&
                         c.x >= tminx - c.z && c.x <= tmaxx + c.z &&
                         c.y >= tminy - c.z && c.y <= tmaxy + c.z);
            unsigned m = __ballot_sync(0xffffffffu, keep);
            if (m) {
                int leader = __ffs(m) - 1;
                int basep = 0;
                if (lane == leader) basep = atomicAdd(&s_cnt, __popc(m));
                basep = __shfl_sync(0xffffffffu, basep, leader);
                if (keep) {
                    unsigned int zb = __float_as_uint(c.w);
                    zb = (zb & 0x80000000u) ? ~zb : (zb | 0x80000000u);
                    int p = basep + __popc(m & ((1u << lane) - 1u));
                    s_key[p] = ((unsigned long long)zb << 32) | (unsigned int)gi;
                }
            }
        }
        __syncthreads();
        int cnt = s_cnt;

        // ---- bitonic sort (exact, stable: index in low bits) ----
        if (cnt > 1) {
            int msz = 1; while (msz < cnt) msz <<= 1;
            for (int i = cnt + tid; i < msz; i += NTHR) s_key[i] = ~0ull;
            __syncthreads();
            for (int k = 2; k <= msz; k <<= 1) {
                for (int j = k >> 1; j > 0; j >>= 1) {
                    for (int i = tid; i < msz; i += NTHR) {
                        int ixj = i ^ j;
                        if (ixj > i) {
                            bool up = ((i & k) == 0);
                            unsigned long long a = s_key[i], b = s_key[ixj];
                            if ((a > b) == up) { s_key[i] = b; s_key[ixj] = a; }
                        }
                    }
                    __syncthreads();
                }
            }
        }

        // ---- gather all survivor params into smem in sorted order ----
        for (int i = tid; i < cnt; i += NTHR) {
            int idx = base + (int)(unsigned int)s_key[i];
            float4 cu = g_cull[idx];
            float4 cl = g_col[idx];
            s_pos[i] = make_float4(cu.x, cu.y, cl.w, cu.w);
            s_con[i] = g_con[idx];
            s_col[i] = cl;
        }
        __syncthreads();

        // ---- segment-parallel blend ----
        float pcx = (float)(tx*TSX + lx) + 0.5f;
        float pcy = (float)(ty*TSY + ly) + 0.5f;
        int L = (cnt + NSEG - 1) / NSEG;
        int j0 = seg * L;
        int j1 = min(j0 + L, cnt);

        float T = 1.f, ar = 0.f, ag = 0.f, ab = 0.f, ad = 0.f;
        for (int j = j0; j < j1; j++) {
            float4 p  = s_pos[j];
            float4 cn = s_con[j];
            float du = pcx - p.x, dv = pcy - p.y;
            // power = -0.5*ia*du^2 - ib*du*dv - 0.5*idd*dv^2 (con premultiplied)
            float power = fmaf(cn.x, du*du, fmaf(cn.z, dv*dv, cn.y*du*dv));
            if (power < p.z) continue;           // alpha < 1/255 guaranteed
            power = fminf(power, 0.f);
            float alpha = fminf(cn.w * __expf(power), 0.99f);
            if (alpha >= (1.0f/255.0f)) {
                float4 cl = s_col[j];
                float w = alpha * T;
                ar += w * cl.x; ag += w * cl.y; ab += w * cl.z;
                ad += w * p.w;
                T *= (1.f - alpha);
                if (T < 1e-5f) break;            // residual < 1e-5 absolute
            }
        }
        segC[seg][pix] = make_float4(ar, ag, ab, ad);
        segT[seg][pix] = T;
        __syncthreads();

        // ---- combine segments front-to-back + store ----
        if (seg == 0) {
            float4 C = segC[0][pix];
            float Tacc = segT[0][pix];
            #pragma unroll
            for (int s = 1; s < NSEG; s++) {
                float4 Cs = segC[s][pix];
                C.x += Tacc * Cs.x; C.y += Tacc * Cs.y;
                C.z += Tacc * Cs.z; C.w += Tacc * Cs.w;
                Tacc *= segT[s][pix];
            }
            int px = tx*TSX + lx, py = ty*TSY + ly;
            if (px < W && py < H) {
                ((float4*)out)[(vi * H + py) * W + px] = C;
            }
        }
    }
}

// ---------------------------------------------------------------------------
extern "C" void kernel_launch(void* const* d_in, const int* in_sizes, int n_in,
                              void* d_out, int out_size)
{
    const float* means  = (const float*)d_in[0];
    const float* scales = (const float*)d_in[1];
    const float* rots   = (const float*)d_in[2];
    const float* sh     = (const float*)d_in[3];
    const float* opac   = (const float*)d_in[4];
    const float* extr   = (const float*)d_in[5];
    const float* intr   = (const float*)d_in[6];
    const int*   Hp     = (const int*)d_in[7];
    const int*   Wp     = (const int*)d_in[8];
    float* out = (float*)d_out;

    int G  = in_sizes[4];        // B = 1 for this instance
    int NV = in_sizes[5] / 16;   // B*N views

    int total = G * NV;
    prep_kernel<<<(total + 63) / 64, 64>>>(means, scales, rots, sh, opac,
                                           extr, intr, Hp, Wp, G, NV);

    size_t dynSmem = (size_t)G * (8 + 16 + 16 + 16);   // keys + pos + con + col
    static int attrSet = 0;
    if (!attrSet) {
        cudaFuncSetAttribute(composite_kernel,
                             cudaFuncAttributeMaxDynamicSharedMemorySize,
                             (int)dynSmem);
        attrSet = 1;
    }
    composite_kernel<<<296, NTHR, dynSmem>>>(out, Hp, Wp, G, NV);
}

// round 5
// speedup vs baseline: 1.1834x; 1.1834x over previous
#include <cuda_runtime.h>
#include <math.h>

#define NSEG 4
#define NPIX 256
#define NTHR 1024
#define TSX 16
#define TSY 16

struct GParam {
    float u, v, rad, z;
    float ca, cb, cc, op;     // premultiplied conic: -0.5*ia, -ib, -0.5*idd
    float cr, cg, cbl, thr;
};

// Full per-gaussian preprocessing (≈250 flops). Called in cull (needs u,v,rad)
// and again at gather for the sorted survivors (needs everything).
__device__ __forceinline__ GParam prep_one(
    int g, const float* __restrict__ means, const float* __restrict__ scales,
    const float* __restrict__ rots, const float* __restrict__ sh,
    const float* __restrict__ opac, const float* __restrict__ E,
    float fx, float fy, float cx, float cy)
{
    GParam r;
    float mx = means[g*3+0], my = means[g*3+1], mz = means[g*3+2];
    float px = E[0]*mx + E[1]*my + E[2]*mz  + E[3];
    float py = E[4]*mx + E[5]*my + E[6]*mz  + E[7];
    float pz = E[8]*mx + E[9]*my + E[10]*mz + E[11];
    float zs = fmaxf(pz, 1e-6f);
    r.z = pz;
    r.u = fx * px / zs + cx;
    r.v = fy * py / zs + cy;

    float4 q4 = ((const float4*)rots)[g];
    float qw = q4.x, qx = q4.y, qy = q4.z, qz = q4.w;
    float qinv = rsqrtf(qw*qw + qx*qx + qy*qy + qz*qz);
    qw *= qinv; qx *= qinv; qy *= qinv; qz *= qinv;
    float R00 = 1.f - 2.f*(qy*qy + qz*qz), R01 = 2.f*(qx*qy - qw*qz), R02 = 2.f*(qx*qz + qw*qy);
    float R10 = 2.f*(qx*qy + qw*qz), R11 = 1.f - 2.f*(qx*qx + qz*qz), R12 = 2.f*(qy*qz - qw*qx);
    float R20 = 2.f*(qx*qz - qw*qy), R21 = 2.f*(qy*qz + qw*qx), R22 = 1.f - 2.f*(qx*qx + qy*qy);

    float s0 = scales[g*3+0], s1 = scales[g*3+1], s2 = scales[g*3+2];
    float M00=R00*s0, M01=R01*s1, M02=R02*s2;
    float M10=R10*s0, M11=R11*s1, M12=R12*s2;
    float M20=R20*s0, M21=R21*s1, M22=R22*s2;
    float S00 = M00*M00+M01*M01+M02*M02;
    float S01 = M00*M10+M01*M11+M02*M12;
    float S02 = M00*M20+M01*M21+M02*M22;
    float S11 = M10*M10+M11*M11+M12*M12;
    float S12 = M10*M20+M11*M21+M12*M22;
    float S22 = M20*M20+M21*M21+M22*M22;

    float iz  = 1.f / zs;
    float J00 = fx*iz,  J02 = -fx*px*iz*iz;
    float J11 = fy*iz,  J12 = -fy*py*iz*iz;
    float t00 = J00*E[0] + J02*E[8];
    float t01 = J00*E[1] + J02*E[9];
    float t02 = J00*E[2] + J02*E[10];
    float t10 = J11*E[4] + J12*E[8];
    float t11 = J11*E[5] + J12*E[9];
    float t12 = J11*E[6] + J12*E[10];
    float w0 = S00*t00 + S01*t01 + S02*t02;
    float w1 = S01*t00 + S11*t01 + S12*t02;
    float w2 = S02*t00 + S12*t01 + S22*t02;
    float a  = t00*w0 + t01*w1 + t02*w2 + 0.3f;
    float b  = t10*w0 + t11*w1 + t12*w2;
    float x0 = S00*t10 + S01*t11 + S02*t12;
    float x1 = S01*t10 + S11*t11 + S12*t12;
    float x2 = S02*t10 + S12*t11 + S22*t12;
    float d  = t10*x0 + t11*x1 + t12*x2 + 0.3f;

    float det = a*d - b*b;
    float ds  = fmaxf(det, 1e-12f);
    bool valid = (pz > 0.2f) && (det > 1e-12f);
    float op = valid ? opac[g] : 0.f;
    r.op = op;
    r.ca = -0.5f * (d/ds);
    r.cb = -(-b/ds);
    r.cc = -0.5f * (a/ds);

    const float SH_C0 = 0.28209479177387814f;
    r.cr  = fmaxf(SH_C0 * sh[g*3+0] + 0.5f, 0.f);
    r.cg  = fmaxf(SH_C0 * sh[g*3+1] + 0.5f, 0.f);
    r.cbl = fmaxf(SH_C0 * sh[g*3+2] + 0.5f, 0.f);

    // Conservative cull radius: alpha >= 1/255 needs 0.5 d^T C d <= ln(255 op);
    // via lmin(C)=1/lmax(cov2D): |d| <= sqrt(2 ln(255 op) lmax(cov2D)).
    r.rad = -1.f;
    r.thr = 0.f;
    if (op * 255.f > 1.f) {
        float lam = 0.5f*(a+d) + sqrtf(0.25f*(a-d)*(a-d) + b*b);
        float t = logf(255.f * op);
        r.rad = sqrtf(fmaxf(2.f*t*lam, 0.f)) + 0.05f;
        r.thr = -t - 1e-4f;   // power < thr => alpha < 1/255 guaranteed
    }
    return r;
}

// ---------------------------------------------------------------------------
// Single fused kernel: per-tile prep+cull -> rank sort -> gather -> blend.
// 1024 threads = 4 depth segments x 256 pixels (16x16 tile).
// ---------------------------------------------------------------------------
__global__ __launch_bounds__(NTHR, 1)
void splat_kernel(float* __restrict__ out,
                  const float* __restrict__ means,
                  const float* __restrict__ scales,
                  const float* __restrict__ rots,
                  const float* __restrict__ sh,
                  const float* __restrict__ opac,
                  const float* __restrict__ extr,
                  const float* __restrict__ intr,
                  const int* __restrict__ Hp,
                  const int* __restrict__ Wp,
                  int G, int NV)
{
    int W = *Wp, H = *Hp;
    int ntx = (W + TSX - 1) / TSX, nty = (H + TSY - 1) / TSY;
    int totalTiles = ntx * nty * NV;

    extern __shared__ char dsm[];
    float4* s_pos = (float4*)dsm;                 // (u,v,thr,z)      G*16
    float4* s_con = s_pos + G;                    // (ca,cb,cc,op)    G*16
    float4* s_col = s_con + G;                    // (cr,cg,cb,-)     G*16
    unsigned long long* s_key = (unsigned long long*)(s_col + G);  // G*8
    int* s_sid = (int*)(s_key + G);               // sorted gaussian idx, G*4
    __shared__ float4 segC[NSEG][NPIX];
    __shared__ float  segT[NSEG][NPIX];
    __shared__ int s_cnt;

    int tid = threadIdx.x;
    int lane = tid & 31;
    int seg = tid >> 8, pix = tid & (NPIX - 1);
    int lx = pix & (TSX - 1), ly = pix >> 4;

    for (int tile = blockIdx.x; tile < totalTiles; tile += gridDim.x) {
        int vi = tile / (ntx * nty);
        int t2 = tile - vi * ntx * nty;
        int tx = t2 % ntx, ty = t2 / ntx;

        const float* E = extr + vi * 16;
        const float* K = intr + vi * 9;
        float Wf = (float)W, Hf = (float)H;
        float fx = (K[0] / Wf) * Wf;
        float cx = (K[2] / Wf) * Wf;
        float fy = (K[4] / Hf) * Hf;
        float cy = (K[5] / Hf) * Hf;

        float tminx = (float)(tx*TSX), tmaxx = (float)(tx*TSX + TSX);
        float tminy = (float)(ty*TSY), tmaxy = (float)(ty*TSY + TSY);

        __syncthreads();
        if (tid == 0) s_cnt = 0;
        __syncthreads();

        // ---- fused prep + cull: append (flipped z bits | index) keys ----
        for (int gi = tid; gi < G; gi += NTHR) {
            GParam p = prep_one(gi, means, scales, rots, sh, opac, E, fx, fy, cx, cy);
            bool keep = (p.rad > 0.f &&
                         p.u >= tminx - p.rad && p.u <= tmaxx + p.rad &&
                         p.v >= tminy - p.rad && p.v <= tmaxy + p.rad);
            unsigned m = __ballot_sync(0xffffffffu, keep);
            if (m) {
                int leader = __ffs(m) - 1;
                int basep = 0;
                if (lane == leader) basep = atomicAdd(&s_cnt, __popc(m));
                basep = __shfl_sync(0xffffffffu, basep, leader);
                if (keep) {
                    unsigned int zb = __float_as_uint(p.z);
                    zb = (zb & 0x80000000u) ? ~zb : (zb | 0x80000000u);
                    int pp = basep + __popc(m & ((1u << lane) - 1u));
                    s_key[pp] = ((unsigned long long)zb << 32) | (unsigned int)gi;
                }
            }
        }
        __syncthreads();
        int cnt = s_cnt;

        // ---- exact rank sort (keys unique -> rank is a permutation) ----
        for (int i = tid; i < cnt; i += NTHR) {
            unsigned long long k = s_key[i];
            int r = 0;
            for (int j = 0; j < cnt; j++) r += (s_key[j] < k);
            s_sid[r] = (int)(unsigned int)k;
        }
        __syncthreads();

        // ---- gather: recompute prep for sorted survivors into smem ----
        for (int i = tid; i < cnt; i += NTHR) {
            GParam p = prep_one(s_sid[i], means, scales, rots, sh, opac, E, fx, fy, cx, cy);
            s_pos[i] = make_float4(p.u, p.v, p.thr, p.z);
            s_con[i] = make_float4(p.ca, p.cb, p.cc, p.op);
            s_col[i] = make_float4(p.cr, p.cg, p.cbl, 0.f);
        }
        __syncthreads();

        // ---- segment-parallel front-to-back blend ----
        float pcx = (float)(tx*TSX + lx) + 0.5f;
        float pcy = (float)(ty*TSY + ly) + 0.5f;
        int L = (cnt + NSEG - 1) / NSEG;
        int j0 = seg * L;
        int j1 = min(j0 + L, cnt);

        float T = 1.f, ar = 0.f, ag = 0.f, ab = 0.f, ad = 0.f;
        for (int j = j0; j < j1; j++) {
            float4 p  = s_pos[j];
            float4 cn = s_con[j];
            float du = pcx - p.x, dv = pcy - p.y;
            float power = fmaf(cn.x, du*du, fmaf(cn.z, dv*dv, cn.y*du*dv));
            if (power < p.z) continue;           // alpha < 1/255 guaranteed
            power = fminf(power, 0.f);
            float alpha = fminf(cn.w * __expf(power), 0.99f);
            if (alpha >= (1.0f/255.0f)) {
                float4 cl = s_col[j];
                float w = alpha * T;
                ar += w * cl.x; ag += w * cl.y; ab += w * cl.z;
                ad += w * p.w;
                T *= (1.f - alpha);
                if (T < 1e-5f) break;            // residual < 1e-5 absolute
            }
        }
        segC[seg][pix] = make_float4(ar, ag, ab, ad);
        segT[seg][pix] = T;
        __syncthreads();

        // ---- combine segments front-to-back + store ----
        if (seg == 0) {
            float4 C = segC[0][pix];
            float Tacc = segT[0][pix];
            #pragma unroll
            for (int s = 1; s < NSEG; s++) {
                float4 Cs = segC[s][pix];
                C.x += Tacc * Cs.x; C.y += Tacc * Cs.y;
                C.z += Tacc * Cs.z; C.w += Tacc * Cs.w;
                Tacc *= segT[s][pix];
            }
            int px = tx*TSX + lx, py = ty*TSY + ly;
            if (px < W && py < H) {
                ((float4*)out)[(vi * H + py) * W + px] = C;
            }
        }
    }
}

// ---------------------------------------------------------------------------
extern "C" void kernel_launch(void* const* d_in, const int* in_sizes, int n_in,
                              void* d_out, int out_size)
{
    const float* means  = (const float*)d_in[0];
    const float* scales = (const float*)d_in[1];
    const float* rots   = (const float*)d_in[2];
    const float* sh     = (const float*)d_in[3];
    const float* opac   = (const float*)d_in[4];
    const float* extr   = (const float*)d_in[5];
    const float* intr   = (const float*)d_in[6];
    const int*   Hp     = (const int*)d_in[7];
    const int*   Wp     = (const int*)d_in[8];
    float* out = (float*)d_out;

    int G  = in_sizes[4];        // B = 1 for this instance
    int NV = in_sizes[5] / 16;   // B*N views

    size_t dynSmem = (size_t)G * (16 + 16 + 16 + 8 + 4);   // pos+con+col+key+sid
    static int attrSet = 0;
    if (!attrSet) {
        cudaFuncSetAttribute(splat_kernel,
                             cudaFuncAttributeMaxDynamicSharedMemorySize,
                             (int)dynSmem);
        attrSet = 1;
    }
    splat_kernel<<<296, NTHR, dynSmem>>>(out, means, scales, rots, sh, opac,
                                         extr, intr, Hp, Wp, G, NV);
}